// round 2
// baseline (speedup 1.0000x reference)
#include <cuda_runtime.h>
#include <math.h>

#define NE 64
#define NH 512
#define NF 2048
#define NT 2048

// scratch: h = gelu(x @ w1^T)  (16 MB), plus expert offsets
__device__ float g_h[(size_t)NT * NF];
__device__ int g_offs[NE + 1];

typedef unsigned long long u64;

__device__ __forceinline__ void fma2(u64& d, u64 a, u64 b) {
    asm("fma.rn.f32x2 %0, %1, %2, %0;" : "+l"(d) : "l"(a), "l"(b));
}
__device__ __forceinline__ float2 unpack2(u64 v) {
    float2 r; asm("mov.b64 {%0, %1}, %2;" : "=f"(r.x), "=f"(r.y) : "l"(v)); return r;
}
__device__ __forceinline__ float gelu_exact(float v) {
    return 0.5f * v * (1.0f + erff(v * 0.7071067811865476f));
}

// ---------------------------------------------------------------------------
__global__ void offs_kernel(const int* __restrict__ counts) {
    __shared__ int s[NE];
    int tid = threadIdx.x;
    if (tid < NE) s[tid] = counts[tid];
    __syncthreads();
    if (tid == 0) {
        int acc = 0;
        g_offs[0] = 0;
        #pragma unroll
        for (int e = 0; e < NE; ++e) { acc += s[e]; g_offs[e + 1] = acc; }
    }
}

// ---------------------------------------------------------------------------
// GEMM1 + GELU: h[t,f] = gelu(sum_k x[t,k] * w1[e,f,k])
// Tile M=16 tok, N=256 f, K=16. 256 threads. Thread tile: 8 tok x 2 f (1 f32x2).
// Double-buffered smem; transposed-k-major B; duplicated A for packed FFMA2.
// ---------------------------------------------------------------------------
#define G1W 258
__global__ __launch_bounds__(256) void gemm1_kernel(
    const float* __restrict__ x, const float* __restrict__ w1)
{
    __shared__ float ws[2][16 * G1W];   // B: [k][n], W=258 -> conflict-free STS+LDS
    __shared__ float xs[2][16 * 36];    // A: [k][2m] duplicated pairs

    const int e  = blockIdx.y;
    const int f0 = blockIdx.x * 256;
    const int base = g_offs[e];
    const int cnt  = g_offs[e + 1] - base;
    const int tid = threadIdx.x;
    const int wid = tid >> 5, l = tid & 31;
    const int tg = wid >> 2;               // token group (8 tokens)
    const int np = l + 32 * (wid & 3);     // f-pair index 0..127
    const int sk4 = (tid & 3) * 4;         // staging k offset
    const int sn  = tid >> 2;              // staging n base 0..63
    const float* w1e = w1 + (size_t)e * NF * NH;
    const int mstep = 16 * gridDim.z;

    for (int mm = blockIdx.z * 16; mm < cnt; mm += mstep) {
        u64 c[8];
        #pragma unroll
        for (int i = 0; i < 8; ++i) c[i] = 0ull;

        float4 wv[4];
        float4 xv = make_float4(0.f, 0.f, 0.f, 0.f);

        // ---- prologue: load k-tile 0 ----
        #pragma unroll
        for (int jj = 0; jj < 4; ++jj)
            wv[jj] = *(const float4*)&w1e[(size_t)(f0 + sn + 64 * jj) * NH + sk4];
        if (tid < 64 && mm + sn < cnt)   // sn==sm for tid<64
            xv = *(const float4*)&x[(size_t)(base + mm + sn) * NH + sk4];
        {   // STS buf 0
            float* wd = ws[0];
            #pragma unroll
            for (int jj = 0; jj < 4; ++jj) {
                const float* v = (const float*)&wv[jj];
                const int n = sn + 64 * jj;
                #pragma unroll
                for (int i = 0; i < 4; ++i) wd[(sk4 + i) * G1W + n] = v[i];
            }
            if (tid < 64) {
                float* xd = xs[0];
                const float* v = (const float*)&xv;
                #pragma unroll
                for (int i = 0; i < 4; ++i)
                    *(float2*)&xd[(sk4 + i) * 36 + 2 * sn] = make_float2(v[i], v[i]);
            }
        }
        __syncthreads();

        int buf = 0;
        for (int kt = 0; kt < 32; ++kt) {
            // prefetch next k-tile into registers
            if (kt + 1 < 32) {
                const int k0 = (kt + 1) * 16;
                #pragma unroll
                for (int jj = 0; jj < 4; ++jj)
                    wv[jj] = *(const float4*)&w1e[(size_t)(f0 + sn + 64 * jj) * NH + k0 + sk4];
                xv = make_float4(0.f, 0.f, 0.f, 0.f);
                if (tid < 64 && mm + sn < cnt)
                    xv = *(const float4*)&x[(size_t)(base + mm + sn) * NH + k0 + sk4];
            }
            // compute on current buffer
            const float* wsb = ws[buf];
            const float* xsb = xs[buf];
            #pragma unroll
            for (int kk = 0; kk < 16; ++kk) {
                const float* ar = xsb + kk * 36 + 16 * tg;
                ulonglong2 a01 = *(const ulonglong2*)(ar);
                ulonglong2 a23 = *(const ulonglong2*)(ar + 4);
                ulonglong2 a45 = *(const ulonglong2*)(ar + 8);
                ulonglong2 a67 = *(const ulonglong2*)(ar + 12);
                u64 b = *(const u64*)(wsb + kk * G1W + 2 * np);
                fma2(c[0], a01.x, b); fma2(c[1], a01.y, b);
                fma2(c[2], a23.x, b); fma2(c[3], a23.y, b);
                fma2(c[4], a45.x, b); fma2(c[5], a45.y, b);
                fma2(c[6], a67.x, b); fma2(c[7], a67.y, b);
            }
            // store prefetched tile into other buffer
            if (kt + 1 < 32) {
                float* wd = ws[buf ^ 1];
                #pragma unroll
                for (int jj = 0; jj < 4; ++jj) {
                    const float* v = (const float*)&wv[jj];
                    const int n = sn + 64 * jj;
                    #pragma unroll
                    for (int i = 0; i < 4; ++i) wd[(sk4 + i) * G1W + n] = v[i];
                }
                if (tid < 64) {
                    float* xd = xs[buf ^ 1];
                    const float* v = (const float*)&xv;
                    #pragma unroll
                    for (int i = 0; i < 4; ++i)
                        *(float2*)&xd[(sk4 + i) * 36 + 2 * sn] = make_float2(v[i], v[i]);
                }
            }
            __syncthreads();
            buf ^= 1;
        }

        // ---- epilogue: GELU + store h ----
        #pragma unroll
        for (int i = 0; i < 8; ++i) {
            const int m = mm + 8 * tg + i;
            if (m < cnt) {
                float2 p = unpack2(c[i]);
                float2 o = make_float2(gelu_exact(p.x), gelu_exact(p.y));
                *(float2*)&g_h[(size_t)(base + m) * NF + f0 + 2 * np] = o;
            }
        }
    }
}

// ---------------------------------------------------------------------------
// GEMM2: out[t,n] = sum_k h[t,k] * w2[e,k,n]   (K=2048, N=512)
// Tile M=16, N=256, K=16. Thread tile 8 tok x 2 n. w2 staged k-major directly.
// ---------------------------------------------------------------------------
#define G2W 260
__global__ __launch_bounds__(256) void gemm2_kernel(
    const float* __restrict__ w2, float* __restrict__ out)
{
    __shared__ float ws2[2][16 * G2W];
    __shared__ float hs[2][16 * 36];

    const int e  = blockIdx.y;
    const int n0 = blockIdx.x * 256;
    const int base = g_offs[e];
    const int cnt  = g_offs[e + 1] - base;
    const int tid = threadIdx.x;
    const int wid = tid >> 5, l = tid & 31;
    const int tg = wid >> 2;
    const int np = l + 32 * (wid & 3);
    const int sn4 = tid & 63;          // w2 staging: float4 col 0..63
    const int skr = tid >> 6;          // w2 staging: row group 0..3
    const int sk4 = (tid & 3) * 4;     // hs staging
    const int sm  = tid >> 2;
    const float* w2e = w2 + (size_t)e * NF * NH;
    const int mstep = 16 * gridDim.z;

    for (int mm = blockIdx.z * 16; mm < cnt; mm += mstep) {
        u64 c[8];
        #pragma unroll
        for (int i = 0; i < 8; ++i) c[i] = 0ull;

        float4 wv[4];
        float4 hv = make_float4(0.f, 0.f, 0.f, 0.f);

        // ---- prologue: load k-tile 0 ----
        #pragma unroll
        for (int jj = 0; jj < 4; ++jj)
            wv[jj] = *(const float4*)&w2e[(size_t)(skr + 4 * jj) * NH + n0 + 4 * sn4];
        if (tid < 64 && mm + sm < cnt)
            hv = *(const float4*)&g_h[(size_t)(base + mm + sm) * NF + sk4];
        {
            float* wd = ws2[0];
            #pragma unroll
            for (int jj = 0; jj < 4; ++jj)
                *(float4*)&wd[(skr + 4 * jj) * G2W + 4 * sn4] = wv[jj];
            if (tid < 64) {
                float* hd = hs[0];
                const float* v = (const float*)&hv;
                #pragma unroll
                for (int i = 0; i < 4; ++i)
                    *(float2*)&hd[(sk4 + i) * 36 + 2 * sm] = make_float2(v[i], v[i]);
            }
        }
        __syncthreads();

        int buf = 0;
        for (int kt = 0; kt < 128; ++kt) {
            if (kt + 1 < 128) {
                const int k0 = (kt + 1) * 16;
                #pragma unroll
                for (int jj = 0; jj < 4; ++jj)
                    wv[jj] = *(const float4*)&w2e[(size_t)(k0 + skr + 4 * jj) * NH + n0 + 4 * sn4];
                hv = make_float4(0.f, 0.f, 0.f, 0.f);
                if (tid < 64 && mm + sm < cnt)
                    hv = *(const float4*)&g_h[(size_t)(base + mm + sm) * NF + k0 + sk4];
            }
            const float* wsb = ws2[buf];
            const float* hsb = hs[buf];
            #pragma unroll
            for (int kk = 0; kk < 16; ++kk) {
                const float* ar = hsb + kk * 36 + 16 * tg;
                ulonglong2 a01 = *(const ulonglong2*)(ar);
                ulonglong2 a23 = *(const ulonglong2*)(ar + 4);
                ulonglong2 a45 = *(const ulonglong2*)(ar + 8);
                ulonglong2 a67 = *(const ulonglong2*)(ar + 12);
                u64 b = *(const u64*)(wsb + kk * G2W + 2 * np);
                fma2(c[0], a01.x, b); fma2(c[1], a01.y, b);
                fma2(c[2], a23.x, b); fma2(c[3], a23.y, b);
                fma2(c[4], a45.x, b); fma2(c[5], a45.y, b);
                fma2(c[6], a67.x, b); fma2(c[7], a67.y, b);
            }
            if (kt + 1 < 128) {
                float* wd = ws2[buf ^ 1];
                #pragma unroll
                for (int jj = 0; jj < 4; ++jj)
                    *(float4*)&wd[(skr + 4 * jj) * G2W + 4 * sn4] = wv[jj];
                if (tid < 64) {
                    float* hd = hs[buf ^ 1];
                    const float* v = (const float*)&hv;
                    #pragma unroll
                    for (int i = 0; i < 4; ++i)
                        *(float2*)&hd[(sk4 + i) * 36 + 2 * sm] = make_float2(v[i], v[i]);
                }
            }
            __syncthreads();
            buf ^= 1;
        }

        #pragma unroll
        for (int i = 0; i < 8; ++i) {
            const int m = mm + 8 * tg + i;
            if (m < cnt) {
                float2 p = unpack2(c[i]);
                *(float2*)&out[(size_t)(base + m) * NH + n0 + 2 * np] = p;
            }
        }
    }
}

// ---------------------------------------------------------------------------
extern "C" void kernel_launch(void* const* d_in, const int* in_sizes, int n_in,
                              void* d_out, int out_size) {
    const float* x  = (const float*)d_in[0];
    const float* w1 = (const float*)d_in[1];
    const float* w2 = (const float*)d_in[2];
    const int* tokens_per_expert = (const int*)d_in[3];
    float* out = (float*)d_out;

    offs_kernel<<<1, 64>>>(tokens_per_expert);
    gemm1_kernel<<<dim3(NF / 256, NE, 3), 256>>>(x, w1);
    gemm2_kernel<<<dim3(NH / 256, NE, 3), 256>>>(w2, out);
}

// round 4
// speedup vs baseline: 2.5364x; 2.5364x over previous
#include <cuda_runtime.h>
#include <math.h>
#include <stdint.h>

#define NE 64
#define NH 512
#define NF 2048
#define NT 2048

// scratch: h = gelu(x @ w1^T) (16 MB) + expert offsets
__device__ float g_h[(size_t)NT * NF];
__device__ int g_offs[NE + 1];

// ---------------- helpers ----------------
__device__ __forceinline__ uint32_t smem_u32(const void* p) {
    return (uint32_t)__cvta_generic_to_shared(p);
}
__device__ __forceinline__ uint32_t sw128(uint32_t off) { return off ^ ((off >> 3) & 0x70); }

__device__ __forceinline__ void ldm_x4(uint32_t* r, uint32_t a) {
    asm volatile("ldmatrix.sync.aligned.m8n8.x4.shared.b16 {%0,%1,%2,%3}, [%4];"
                 : "=r"(r[0]), "=r"(r[1]), "=r"(r[2]), "=r"(r[3]) : "r"(a));
}
__device__ __forceinline__ void ldm_x4_t(uint32_t* r, uint32_t a) {
    asm volatile("ldmatrix.sync.aligned.m8n8.x4.trans.shared.b16 {%0,%1,%2,%3}, [%4];"
                 : "=r"(r[0]), "=r"(r[1]), "=r"(r[2]), "=r"(r[3]) : "r"(a));
}
__device__ __forceinline__ void mma_bf16(float* c, const uint32_t* a, const uint32_t* b) {
    asm volatile(
        "mma.sync.aligned.m16n8k16.row.col.f32.bf16.bf16.f32 "
        "{%0,%1,%2,%3}, {%4,%5,%6,%7}, {%8,%9}, {%0,%1,%2,%3};"
        : "+f"(c[0]), "+f"(c[1]), "+f"(c[2]), "+f"(c[3])
        : "r"(a[0]), "r"(a[1]), "r"(a[2]), "r"(a[3]), "r"(b[0]), "r"(b[1]));
}
__device__ __forceinline__ float gelu_exact(float v) {
    return 0.5f * v * (1.0f + erff(v * 0.7071067811865476f));
}

// ---------------- offsets ----------------
__global__ void offs_kernel(const int* __restrict__ counts) {
    __shared__ int s[NE];
    int tid = threadIdx.x;
    if (tid < NE) s[tid] = counts[tid];
    __syncthreads();
    if (tid == 0) {
        int acc = 0;
        g_offs[0] = 0;
        #pragma unroll
        for (int e = 0; e < NE; ++e) { acc += s[e]; g_offs[e + 1] = acc; }
    }
}

// ---------------- f32 tile load (regs) + split-convert store (smem) ----------
// Tile: R rows x 64 f32 cols. 256 threads: 16 threads/row (float4), 16 rows/pass.
template<int R>
__device__ __forceinline__ void load_f32(float4* v, const float* __restrict__ src,
                                         int stride, int valid, int tid) {
    const int row0 = tid >> 4, c4 = (tid & 15) * 4;
    #pragma unroll
    for (int p = 0; p < R / 16; ++p) {
        const int row = p * 16 + row0;
        v[p] = (row < valid) ? *(const float4*)(src + (size_t)row * stride + c4)
                             : make_float4(0.f, 0.f, 0.f, 0.f);
    }
}
template<int R>
__device__ __forceinline__ void store_split(const float4* v, char* hi, char* lo, int tid) {
    const int row0 = tid >> 4, l15 = tid & 15;
    #pragma unroll
    for (int p = 0; p < R / 16; ++p) {
        const int row = p * 16 + row0;
        const float4 t = v[p];
        uint32_t h01, h23, l01, l23;
        asm("cvt.rn.bf16x2.f32 %0, %1, %2;" : "=r"(h01) : "f"(t.y), "f"(t.x));
        asm("cvt.rn.bf16x2.f32 %0, %1, %2;" : "=r"(h23) : "f"(t.w), "f"(t.z));
        const float rx = t.x - __uint_as_float(h01 << 16);
        const float ry = t.y - __uint_as_float(h01 & 0xffff0000u);
        const float rz = t.z - __uint_as_float(h23 << 16);
        const float rw = t.w - __uint_as_float(h23 & 0xffff0000u);
        asm("cvt.rn.bf16x2.f32 %0, %1, %2;" : "=r"(l01) : "f"(ry), "f"(rx));
        asm("cvt.rn.bf16x2.f32 %0, %1, %2;" : "=r"(l23) : "f"(rw), "f"(rz));
        const uint32_t off = sw128((uint32_t)(row * 128 + l15 * 8));
        *(uint64_t*)(hi + off) = ((uint64_t)h23 << 32) | h01;
        *(uint64_t*)(lo + off) = ((uint64_t)l23 << 32) | l01;
    }
}

// Buffer layouts (bytes):
// GEMM1: [Ahi 8K][Alo 8K][Bhi 16K][Blo 16K] = 48K per buffer, x2
// GEMM2: [Ahi 8K][Alo 8K][Bhi  8K][Blo  8K] = 32K per buffer, x2
#define B1 (48 * 1024)
#define B2 (32 * 1024)

// ---------------- GEMM1 + GELU: h = gelu(x @ w1[e]^T) ------------------------
// CTA: (f-slab 128, expert). M=64 padded, K-tiles of 64 (8 tiles).
// 8 warps = 2(m) x 4(n); warp tile 32m x 32n.
__global__ void __launch_bounds__(256, 1) gemm1_tc(const float* __restrict__ x,
                                                   const float* __restrict__ w1) {
    extern __shared__ char sm[];
    const int e  = blockIdx.y;
    const int f0 = blockIdx.x * 128;
    const int base = g_offs[e];
    const int cnt  = g_offs[e + 1] - base;
    const int tid = threadIdx.x, warp = tid >> 5, lane = tid & 31;
    const int wm = warp >> 2, wn = warp & 3;
    const float* w1e = w1 + (size_t)e * NF * NH + (size_t)f0 * NH;

    // per-lane ldmatrix row/col selectors
    const int arow = lane & 15, acol = lane & 16;                 // A (plain)
    const int brow = (lane & 7) + ((lane >> 1) & 8);              // B (plain, [n][k])
    const int bcol = (lane & 8) * 2;

    for (int mm = 0; mm < cnt; mm += 64) {
        const int rem = cnt - mm;
        const int va = rem < 64 ? rem : 64;
        const float* xa = x + (size_t)(base + mm) * NH;

        float4 rA[4], rB[8];
        load_f32<64>(rA, xa, NH, va, tid);
        load_f32<128>(rB, w1e, NH, 128, tid);

        float c[2][4][4];
        #pragma unroll
        for (int i = 0; i < 2; ++i)
            #pragma unroll
            for (int j = 0; j < 4; ++j)
                #pragma unroll
                for (int q = 0; q < 4; ++q) c[i][j][q] = 0.f;

        #pragma unroll 2
        for (int kt = 0; kt < 8; ++kt) {
            char* bb = sm + (kt & 1) * B1;
            store_split<64>(rA, bb, bb + 8 * 1024, tid);
            store_split<128>(rB, bb + 16 * 1024, bb + 32 * 1024, tid);
            __syncthreads();
            if (kt + 1 < 8) {
                const int k0 = (kt + 1) * 64;
                load_f32<64>(rA, xa + k0, NH, va, tid);
                load_f32<128>(rB, w1e + k0, NH, 128, tid);
            }
            const uint32_t uAh = smem_u32(bb), uAl = uAh + 8 * 1024;
            const uint32_t uBh = uAh + 16 * 1024, uBl = uAh + 32 * 1024;
            #pragma unroll
            for (int kk = 0; kk < 4; ++kk) {
                uint32_t ah[2][4], al[2][4];
                #pragma unroll
                for (int mi = 0; mi < 2; ++mi) {
                    const uint32_t off =
                        sw128((uint32_t)((wm * 32 + mi * 16 + arow) * 128 + kk * 32 + acol));
                    ldm_x4(ah[mi], uAh + off);
                    ldm_x4(al[mi], uAl + off);
                }
                uint32_t bh[2][4], bl[2][4];
                #pragma unroll
                for (int nb = 0; nb < 2; ++nb) {
                    const uint32_t off =
                        sw128((uint32_t)((wn * 32 + nb * 16 + brow) * 128 + kk * 32 + bcol));
                    ldm_x4(bh[nb], uBh + off);
                    ldm_x4(bl[nb], uBl + off);
                }
                #pragma unroll
                for (int mi = 0; mi < 2; ++mi)
                    #pragma unroll
                    for (int nb = 0; nb < 2; ++nb)
                        #pragma unroll
                        for (int j = 0; j < 2; ++j) {
                            float* cc = c[mi][nb * 2 + j];
                            mma_bf16(cc, ah[mi], &bh[nb][j * 2]);
                            mma_bf16(cc, ah[mi], &bl[nb][j * 2]);
                            mma_bf16(cc, al[mi], &bh[nb][j * 2]);
                        }
            }
        }

        // epilogue: GELU + store
        const int r0 = lane >> 2, cp = (lane & 3) * 2;
        #pragma unroll
        for (int mi = 0; mi < 2; ++mi)
            #pragma unroll
            for (int nj = 0; nj < 4; ++nj) {
                const int rloc = wm * 32 + mi * 16 + r0;
                const int ncol = f0 + wn * 32 + nj * 8 + cp;
                if (rloc < va) {
                    float2 o = make_float2(gelu_exact(c[mi][nj][0]), gelu_exact(c[mi][nj][1]));
                    *(float2*)&g_h[(size_t)(base + mm + rloc) * NF + ncol] = o;
                }
                if (rloc + 8 < va) {
                    float2 o = make_float2(gelu_exact(c[mi][nj][2]), gelu_exact(c[mi][nj][3]));
                    *(float2*)&g_h[(size_t)(base + mm + rloc + 8) * NF + ncol] = o;
                }
            }
    }
}

// ---------------- GEMM2: out = h @ w2[e]  (w2 is [k][n] -> ldmatrix.trans) ---
// CTA: (n-slab 64, expert). M=64 padded, K-tiles of 64 (32 tiles).
// 8 warps = 2(m) x 4(n); warp tile 32m x 16n.
__global__ void __launch_bounds__(256, 1) gemm2_tc(const float* __restrict__ w2,
                                                   float* __restrict__ out) {
    extern __shared__ char sm[];
    const int e  = blockIdx.y;
    const int n0 = blockIdx.x * 64;
    const int base = g_offs[e];
    const int cnt  = g_offs[e + 1] - base;
    const int tid = threadIdx.x, warp = tid >> 5, lane = tid & 31;
    const int wm = warp >> 2, wn = warp & 3;
    const float* w2e = w2 + (size_t)e * NF * NH + n0;

    const int arow = lane & 15, acol = lane & 16;   // A (plain)
    const int tbrow = lane & 15, tbcol = lane & 16; // B (trans, [k][n])

    for (int mm = 0; mm < cnt; mm += 64) {
        const int rem = cnt - mm;
        const int va = rem < 64 ? rem : 64;
        const float* ha = g_h + (size_t)(base + mm) * NF;

        float4 rA[4], rB[4];
        load_f32<64>(rA, ha, NF, va, tid);
        load_f32<64>(rB, w2e, NH, 64, tid);

        float c[2][2][4];
        #pragma unroll
        for (int i = 0; i < 2; ++i)
            #pragma unroll
            for (int j = 0; j < 2; ++j)
                #pragma unroll
                for (int q = 0; q < 4; ++q) c[i][j][q] = 0.f;

        #pragma unroll 2
        for (int kt = 0; kt < 32; ++kt) {
            char* bb = sm + (kt & 1) * B2;
            store_split<64>(rA, bb, bb + 8 * 1024, tid);
            store_split<64>(rB, bb + 16 * 1024, bb + 24 * 1024, tid);
            __syncthreads();
            if (kt + 1 < 32) {
                const int k0 = (kt + 1) * 64;
                load_f32<64>(rA, ha + k0, NF, va, tid);
                load_f32<64>(rB, w2e + (size_t)k0 * NH, NH, 64, tid);
            }
            const uint32_t uAh = smem_u32(bb), uAl = uAh + 8 * 1024;
            const uint32_t uBh = uAh + 16 * 1024, uBl = uAh + 24 * 1024;
            #pragma unroll
            for (int kk = 0; kk < 4; ++kk) {
                uint32_t ah[2][4], al[2][4];
                #pragma unroll
                for (int mi = 0; mi < 2; ++mi) {
                    const uint32_t off =
                        sw128((uint32_t)((wm * 32 + mi * 16 + arow) * 128 + kk * 32 + acol));
                    ldm_x4(ah[mi], uAh + off);
                    ldm_x4(al[mi], uAl + off);
                }
                uint32_t bh[4], bl[4];
                {
                    const uint32_t off =
                        sw128((uint32_t)((kk * 16 + tbrow) * 128 + wn * 32 + tbcol));
                    ldm_x4_t(bh, uBh + off);
                    ldm_x4_t(bl, uBl + off);
                }
                #pragma unroll
                for (int mi = 0; mi < 2; ++mi)
                    #pragma unroll
                    for (int j = 0; j < 2; ++j) {
                        float* cc = c[mi][j];
                        mma_bf16(cc, ah[mi], &bh[j * 2]);
                        mma_bf16(cc, ah[mi], &bl[j * 2]);
                        mma_bf16(cc, al[mi], &bh[j * 2]);
                    }
            }
        }

        const int r0 = lane >> 2, cp = (lane & 3) * 2;
        #pragma unroll
        for (int mi = 0; mi < 2; ++mi)
            #pragma unroll
            for (int nj = 0; nj < 2; ++nj) {
                const int rloc = wm * 32 + mi * 16 + r0;
                const int ncol = n0 + wn * 16 + nj * 8 + cp;
                if (rloc < va)
                    *(float2*)&out[(size_t)(base + mm + rloc) * NH + ncol] =
                        make_float2(c[mi][nj][0], c[mi][nj][1]);
                if (rloc + 8 < va)
                    *(float2*)&out[(size_t)(base + mm + rloc + 8) * NH + ncol] =
                        make_float2(c[mi][nj][2], c[mi][nj][3]);
            }
    }
}

// ---------------------------------------------------------------------------
extern "C" void kernel_launch(void* const* d_in, const int* in_sizes, int n_in,
                              void* d_out, int out_size) {
    const float* x  = (const float*)d_in[0];
    const float* w1 = (const float*)d_in[1];
    const float* w2 = (const float*)d_in[2];
    const int* tokens_per_expert = (const int*)d_in[3];
    float* out = (float*)d_out;

    cudaFuncSetAttribute(gemm1_tc, cudaFuncAttributeMaxDynamicSharedMemorySize, 2 * B1);
    cudaFuncSetAttribute(gemm2_tc, cudaFuncAttributeMaxDynamicSharedMemorySize, 2 * B2);

    offs_kernel<<<1, 64>>>(tokens_per_expert);
    gemm1_tc<<<dim3(NF / 128, NE), 256, 2 * B1>>>(x, w1);
    gemm2_tc<<<dim3(NH / 64, NE), 256, 2 * B2>>>(w2, out);
}

// round 5
// speedup vs baseline: 3.0898x; 1.2182x over previous
#include <cuda_runtime.h>
#include <math.h>
#include <stdint.h>

#define NE 64
#define NH 512
#define NF 2048
#define NT 2048

// scratch: h = gelu(x @ w1^T) (16 MB)
__device__ float g_h[(size_t)NT * NF];

// ---------------- helpers ----------------
__device__ __forceinline__ uint32_t smem_u32(const void* p) {
    return (uint32_t)__cvta_generic_to_shared(p);
}
__device__ __forceinline__ uint32_t sw128(uint32_t off) { return off ^ ((off >> 3) & 0x70); }

__device__ __forceinline__ void ldm_x4(uint32_t* r, uint32_t a) {
    asm volatile("ldmatrix.sync.aligned.m8n8.x4.shared.b16 {%0,%1,%2,%3}, [%4];"
                 : "=r"(r[0]), "=r"(r[1]), "=r"(r[2]), "=r"(r[3]) : "r"(a));
}
__device__ __forceinline__ void ldm_x4_t(uint32_t* r, uint32_t a) {
    asm volatile("ldmatrix.sync.aligned.m8n8.x4.trans.shared.b16 {%0,%1,%2,%3}, [%4];"
                 : "=r"(r[0]), "=r"(r[1]), "=r"(r[2]), "=r"(r[3]) : "r"(a));
}
__device__ __forceinline__ void mma_bf16(float* c, const uint32_t* a, const uint32_t* b) {
    asm volatile(
        "mma.sync.aligned.m16n8k16.row.col.f32.bf16.bf16.f32 "
        "{%0,%1,%2,%3}, {%4,%5,%6,%7}, {%8,%9}, {%0,%1,%2,%3};"
        : "+f"(c[0]), "+f"(c[1]), "+f"(c[2]), "+f"(c[3])
        : "r"(a[0]), "r"(a[1]), "r"(a[2]), "r"(a[3]), "r"(b[0]), "r"(b[1]));
}
__device__ __forceinline__ float gelu_exact(float v) {
    return 0.5f * v * (1.0f + erff(v * 0.7071067811865476f));
}

// inline expert range: base = sum counts[0..e), cnt = counts[e]
__device__ __forceinline__ void expert_range(const int* __restrict__ counts, int e,
                                             int& base, int& cnt) {
    int b = 0, c = 0;
    #pragma unroll
    for (int j = 0; j < NE; ++j) {
        const int v = __ldg(counts + j);
        if (j < e) b += v;
        if (j == e) c = v;
    }
    base = b; cnt = c;
}

// ---------------- f32 tile load (regs) + split-convert store (smem) ----------
// Tile: R rows x 64 f32 cols. 256 threads: 16 threads/row (float4), 16 rows/pass.
template<int R>
__device__ __forceinline__ void load_f32(float4* v, const float* __restrict__ src,
                                         int stride, int valid, int tid) {
    const int row0 = tid >> 4, c4 = (tid & 15) * 4;
    #pragma unroll
    for (int p = 0; p < R / 16; ++p) {
        const int row = p * 16 + row0;
        v[p] = (row < valid) ? *(const float4*)(src + (size_t)row * stride + c4)
                             : make_float4(0.f, 0.f, 0.f, 0.f);
    }
}
template<int R>
__device__ __forceinline__ void store_split(const float4* v, char* hi, char* lo, int tid) {
    const int row0 = tid >> 4, l15 = tid & 15;
    #pragma unroll
    for (int p = 0; p < R / 16; ++p) {
        const int row = p * 16 + row0;
        const float4 t = v[p];
        uint32_t h01, h23, l01, l23;
        asm("cvt.rn.bf16x2.f32 %0, %1, %2;" : "=r"(h01) : "f"(t.y), "f"(t.x));
        asm("cvt.rn.bf16x2.f32 %0, %1, %2;" : "=r"(h23) : "f"(t.w), "f"(t.z));
        const float rx = t.x - __uint_as_float(h01 << 16);
        const float ry = t.y - __uint_as_float(h01 & 0xffff0000u);
        const float rz = t.z - __uint_as_float(h23 << 16);
        const float rw = t.w - __uint_as_float(h23 & 0xffff0000u);
        asm("cvt.rn.bf16x2.f32 %0, %1, %2;" : "=r"(l01) : "f"(ry), "f"(rx));
        asm("cvt.rn.bf16x2.f32 %0, %1, %2;" : "=r"(l23) : "f"(rw), "f"(rz));
        const uint32_t off = sw128((uint32_t)(row * 128 + l15 * 8));
        *(uint64_t*)(hi + off) = ((uint64_t)h23 << 32) | h01;
        *(uint64_t*)(lo + off) = ((uint64_t)l23 << 32) | l01;
    }
}

// Buffer layouts (bytes), per k-tile stage:
// GEMM1: [Ahi 8K][Alo 8K][Bhi 8K][Blo 8K] = 32K per buffer, x2 = 64K
// GEMM2: [Ahi 8K][Alo 8K][Bhi 8K][Blo 8K] = 32K per buffer, x2 = 64K
#define B1 (32 * 1024)
#define B2 (32 * 1024)

// ---------------- GEMM1 + GELU: h = gelu(x @ w1[e]^T) ------------------------
// CTA: (f-slab 64, expert). M=64 padded, K-tiles of 64 (8 tiles).
// 8 warps = 2(m) x 4(n); warp tile 32m x 16n.
__global__ void __launch_bounds__(256, 2) gemm1_tc(const float* __restrict__ x,
                                                   const float* __restrict__ w1,
                                                   const int* __restrict__ counts) {
    extern __shared__ char sm[];
    const int e  = blockIdx.y;
    const int f0 = blockIdx.x * 64;
    int base, cnt;
    expert_range(counts, e, base, cnt);
    const int tid = threadIdx.x, warp = tid >> 5, lane = tid & 31;
    const int wm = warp >> 2, wn = warp & 3;
    const float* w1e = w1 + (size_t)e * NF * NH + (size_t)f0 * NH;

    // per-lane ldmatrix row/col selectors
    const int arow = lane & 15, acol = lane & 16;        // A (plain)
    const int brow = (lane & 7) + ((lane >> 1) & 8);     // B (plain, [n][k])
    const int bcol = (lane & 8) * 2;

    for (int mm = 0; mm < cnt; mm += 64) {
        const int rem = cnt - mm;
        const int va = rem < 64 ? rem : 64;
        const float* xa = x + (size_t)(base + mm) * NH;

        float4 rA[4], rB[4];
        load_f32<64>(rA, xa, NH, va, tid);
        load_f32<64>(rB, w1e, NH, 64, tid);

        float c[2][2][4];
        #pragma unroll
        for (int i = 0; i < 2; ++i)
            #pragma unroll
            for (int j = 0; j < 2; ++j)
                #pragma unroll
                for (int q = 0; q < 4; ++q) c[i][j][q] = 0.f;

        #pragma unroll 2
        for (int kt = 0; kt < 8; ++kt) {
            char* bb = sm + (kt & 1) * B1;
            store_split<64>(rA, bb, bb + 8 * 1024, tid);
            store_split<64>(rB, bb + 16 * 1024, bb + 24 * 1024, tid);
            __syncthreads();
            if (kt + 1 < 8) {
                const int k0 = (kt + 1) * 64;
                load_f32<64>(rA, xa + k0, NH, va, tid);
                load_f32<64>(rB, w1e + k0, NH, 64, tid);
            }
            const uint32_t uAh = smem_u32(bb), uAl = uAh + 8 * 1024;
            const uint32_t uBh = uAh + 16 * 1024, uBl = uAh + 24 * 1024;
            #pragma unroll
            for (int kk = 0; kk < 4; ++kk) {
                uint32_t ah[2][4], al[2][4];
                #pragma unroll
                for (int mi = 0; mi < 2; ++mi) {
                    const uint32_t off =
                        sw128((uint32_t)((wm * 32 + mi * 16 + arow) * 128 + kk * 32 + acol));
                    ldm_x4(ah[mi], uAh + off);
                    ldm_x4(al[mi], uAl + off);
                }
                uint32_t bh[4], bl[4];
                {
                    const uint32_t off =
                        sw128((uint32_t)((wn * 16 + brow) * 128 + kk * 32 + bcol));
                    ldm_x4(bh, uBh + off);
                    ldm_x4(bl, uBl + off);
                }
                #pragma unroll
                for (int mi = 0; mi < 2; ++mi)
                    #pragma unroll
                    for (int j = 0; j < 2; ++j) {
                        float* cc = c[mi][j];
                        mma_bf16(cc, ah[mi], &bh[j * 2]);
                        mma_bf16(cc, ah[mi], &bl[j * 2]);
                        mma_bf16(cc, al[mi], &bh[j * 2]);
                    }
            }
        }

        // epilogue: GELU + store
        const int r0 = lane >> 2, cp = (lane & 3) * 2;
        #pragma unroll
        for (int mi = 0; mi < 2; ++mi)
            #pragma unroll
            for (int nj = 0; nj < 2; ++nj) {
                const int rloc = wm * 32 + mi * 16 + r0;
                const int ncol = f0 + wn * 16 + nj * 8 + cp;
                if (rloc < va) {
                    float2 o = make_float2(gelu_exact(c[mi][nj][0]), gelu_exact(c[mi][nj][1]));
                    *(float2*)&g_h[(size_t)(base + mm + rloc) * NF + ncol] = o;
                }
                if (rloc + 8 < va) {
                    float2 o = make_float2(gelu_exact(c[mi][nj][2]), gelu_exact(c[mi][nj][3]));
                    *(float2*)&g_h[(size_t)(base + mm + rloc + 8) * NF + ncol] = o;
                }
            }
    }
}

// ---------------- GEMM2: out = h @ w2[e]  (w2 is [k][n] -> ldmatrix.trans) ---
// CTA: (n-slab 64, expert). M=64 padded, K-tiles of 64 (32 tiles).
// 8 warps = 2(m) x 4(n); warp tile 32m x 16n.
__global__ void __launch_bounds__(256, 2) gemm2_tc(const float* __restrict__ w2,
                                                   float* __restrict__ out,
                                                   const int* __restrict__ counts) {
    extern __shared__ char sm[];
    const int e  = blockIdx.y;
    const int n0 = blockIdx.x * 64;
    int base, cnt;
    expert_range(counts, e, base, cnt);
    const int tid = threadIdx.x, warp = tid >> 5, lane = tid & 31;
    const int wm = warp >> 2, wn = warp & 3;
    const float* w2e = w2 + (size_t)e * NF * NH + n0;

    const int arow = lane & 15, acol = lane & 16;   // A (plain)
    const int tbrow = lane & 15, tbcol = lane & 16; // B (trans, [k][n])

    for (int mm = 0; mm < cnt; mm += 64) {
        const int rem = cnt - mm;
        const int va = rem < 64 ? rem : 64;
        const float* ha = g_h + (size_t)(base + mm) * NF;

        float4 rA[4], rB[4];
        load_f32<64>(rA, ha, NF, va, tid);
        load_f32<64>(rB, w2e, NH, 64, tid);

        float c[2][2][4];
        #pragma unroll
        for (int i = 0; i < 2; ++i)
            #pragma unroll
            for (int j = 0; j < 2; ++j)
                #pragma unroll
                for (int q = 0; q < 4; ++q) c[i][j][q] = 0.f;

        #pragma unroll 2
        for (int kt = 0; kt < 32; ++kt) {
            char* bb = sm + (kt & 1) * B2;
            store_split<64>(rA, bb, bb + 8 * 1024, tid);
            store_split<64>(rB, bb + 16 * 1024, bb + 24 * 1024, tid);
            __syncthreads();
            if (kt + 1 < 32) {
                const int k0 = (kt + 1) * 64;
                load_f32<64>(rA, ha + k0, NF, va, tid);
                load_f32<64>(rB, w2e + (size_t)k0 * NH, NH, 64, tid);
            }
            const uint32_t uAh = smem_u32(bb), uAl = uAh + 8 * 1024;
            const uint32_t uBh = uAh + 16 * 1024, uBl = uAh + 24 * 1024;
            #pragma unroll
            for (int kk = 0; kk < 4; ++kk) {
                uint32_t ah[2][4], al[2][4];
                #pragma unroll
                for (int mi = 0; mi < 2; ++mi) {
                    const uint32_t off =
                        sw128((uint32_t)((wm * 32 + mi * 16 + arow) * 128 + kk * 32 + acol));
                    ldm_x4(ah[mi], uAh + off);
                    ldm_x4(al[mi], uAl + off);
                }
                uint32_t bh[4], bl[4];
                {
                    const uint32_t off =
                        sw128((uint32_t)((kk * 16 + tbrow) * 128 + wn * 32 + tbcol));
                    ldm_x4_t(bh, uBh + off);
                    ldm_x4_t(bl, uBl + off);
                }
                #pragma unroll
                for (int mi = 0; mi < 2; ++mi)
                    #pragma unroll
                    for (int j = 0; j < 2; ++j) {
                        float* cc = c[mi][j];
                        mma_bf16(cc, ah[mi], &bh[j * 2]);
                        mma_bf16(cc, ah[mi], &bl[j * 2]);
                        mma_bf16(cc, al[mi], &bh[j * 2]);
                    }
            }
        }

        const int r0 = lane >> 2, cp = (lane & 3) * 2;
        #pragma unroll
        for (int mi = 0; mi < 2; ++mi)
            #pragma unroll
            for (int nj = 0; nj < 2; ++nj) {
                const int rloc = wm * 32 + mi * 16 + r0;
                const int ncol = n0 + wn * 16 + nj * 8 + cp;
                if (rloc < va)
                    *(float2*)&out[(size_t)(base + mm + rloc) * NH + ncol] =
                        make_float2(c[mi][nj][0], c[mi][nj][1]);
                if (rloc + 8 < va)
                    *(float2*)&out[(size_t)(base + mm + rloc + 8) * NH + ncol] =
                        make_float2(c[mi][nj][2], c[mi][nj][3]);
            }
    }
}

// ---------------------------------------------------------------------------
extern "C" void kernel_launch(void* const* d_in, const int* in_sizes, int n_in,
                              void* d_out, int out_size) {
    const float* x  = (const float*)d_in[0];
    const float* w1 = (const float*)d_in[1];
    const float* w2 = (const float*)d_in[2];
    const int* tokens_per_expert = (const int*)d_in[3];
    float* out = (float*)d_out;

    cudaFuncSetAttribute(gemm1_tc, cudaFuncAttributeMaxDynamicSharedMemorySize, 2 * B1);
    cudaFuncSetAttribute(gemm2_tc, cudaFuncAttributeMaxDynamicSharedMemorySize, 2 * B2);

    gemm1_tc<<<dim3(NF / 64, NE), 256, 2 * B1>>>(x, w1, tokens_per_expert);
    gemm2_tc<<<dim3(NH / 64, NE), 256, 2 * B2>>>(w2, out, tokens_per_expert);
}